// round 6
// baseline (speedup 1.0000x reference)
#include <cuda_runtime.h>
#include <cstddef>
#include <cstdint>

#define N_NODES 100000
#define N_EDGES 1000000
#define G_GRAPHS 1024
#define S_SUB 128
#define HID 64
#define EDGE_F 32
#define OUT_F 32
#define L_LAYERS 3
#define BN_EPS 1e-5f

#define E_TILES_TOTAL 15625
#define E_GRID 2048
#define N_TILES 1563
#define N_GRID 512

// ---------------- device scratch ----------------
__device__ float d_z[N_NODES * HID];
__device__ float d_agg[N_NODES * HID];
__device__ float d_bnsum[2 * HID];
__device__ float d_bnABL[(L_LAYERS + 1) * 2 * HID];
__device__ int   d_ncount;
__device__ float d_gsum[G_GRAPHS * L_LAYERS * HID];
__device__ float d_gcnt[G_GRAPHS];
__device__ float d_svec[S_SUB * HID];
__device__ float d_snorm[S_SUB];
__device__ float d_t1[S_SUB * HID];
__device__ float d_t2[S_SUB * HID];

__device__ __forceinline__ void red4(float* addr, float4 v) {
    asm volatile("red.global.add.v4.f32 [%0], {%1,%2,%3,%4};"
                 :: "l"(addr), "f"(v.x), "f"(v.y), "f"(v.z), "f"(v.w)
                 : "memory");
}

__device__ __forceinline__ float f2tf(float x) {
    uint32_t r;
    asm("cvt.rna.tf32.f32 %0, %1;" : "=r"(r) : "f"(x));
    return __uint_as_float(r);
}

__device__ __forceinline__ void mma8(float* d, uint32_t a0, uint32_t a1,
                                     uint32_t a2, uint32_t a3,
                                     uint32_t b0, uint32_t b1) {
    asm volatile(
        "mma.sync.aligned.m16n8k8.row.col.f32.tf32.tf32.f32 "
        "{%0,%1,%2,%3}, {%4,%5,%6,%7}, {%8,%9}, {%0,%1,%2,%3};"
        : "+f"(d[0]), "+f"(d[1]), "+f"(d[2]), "+f"(d[3])
        : "r"(a0), "r"(a1), "r"(a2), "r"(a3), "r"(b0), "r"(b1));
}

#define SA_E 36
#define S68 68

__global__ void init_ab() {
    int c = threadIdx.x;
    d_bnABL[c] = 1.f;
    d_bnABL[64 + c] = 0.f;
    if (c == 0) d_ncount = 0;
}

// =====================================================================
// Fused edge kernel: grid-stride multi-tile, early h[src] gather
// =====================================================================
#define E_SMEM_FLOATS (32*S68 + 64*S68 + 64 + 64 + 64*SA_E + 64*S68)

__global__ __launch_bounds__(128)
void edge_kernel(const float* __restrict__ edge_attr,
                 const int* __restrict__ eidx,
                 const float* __restrict__ w1, const float* __restrict__ b1,
                 const float* __restrict__ w2, const float* __restrict__ b2,
                 const float* __restrict__ ab) {
    extern __shared__ float smem[];
    float* sW1 = smem;                    // [32][68] tf32
    float* sW2 = sW1 + 32 * S68;          // [64][68] tf32
    float* sB1 = sW2 + 64 * S68;
    float* sB2 = sB1 + 64;
    float* sA  = sB2 + 64;                // [64][36]
    float* sH  = sA + 64 * SA_E;          // [64][68]

    const int tid = threadIdx.x;
    const int lane = tid & 31, warp = tid >> 5;
    const int quad = lane >> 2, tq = lane & 3;
    const int r0 = warp * 16;
    const int tc = tid & 7, tr = tid >> 3;
    const int cc = tc * 8, rr = tr * 4;

    for (int i = tid; i < 512; i += 128) {
        float4 v = ((const float4*)w1)[i];
        float* d = sW1 + (i >> 4) * S68 + (i & 15) * 4;
        d[0] = f2tf(v.x); d[1] = f2tf(v.y); d[2] = f2tf(v.z); d[3] = f2tf(v.w);
    }
    for (int i = tid; i < 1024; i += 128) {
        float4 v = ((const float4*)w2)[i];
        float* d = sW2 + (i >> 4) * S68 + (i & 15) * 4;
        d[0] = f2tf(v.x); d[1] = f2tf(v.y); d[2] = f2tf(v.z); d[3] = f2tf(v.w);
    }
    if (tid < 64) { sB1[tid] = b1[tid]; sB2[tid] = b2[tid]; }

    const float4 ax0 = *((const float4*)(ab + cc));
    const float4 ax1 = *((const float4*)(ab + cc + 4));
    const float4 bx0 = *((const float4*)(ab + 64 + cc));
    const float4 bx1 = *((const float4*)(ab + 64 + cc + 4));

    for (int tile = blockIdx.x; tile < E_TILES_TOTAL; tile += E_GRID) {
        const int e0 = tile * 64;

        for (int i = tid; i < 512; i += 128) {
            int r = i >> 3, q = i & 7;
            float4 v = ((const float4*)(edge_attr + (size_t)(e0 + r) * EDGE_F))[q];
            float* d = sA + r * SA_E + q * 4;
            d[0] = f2tf(v.x); d[1] = f2tf(v.y); d[2] = f2tf(v.z); d[3] = f2tf(v.w);
        }
        __syncthreads();

        // ---- EARLY gather: issue h[src] loads before the GEMMs ----
        int vsrc[4], vdst[4];
        float4 hg0[4], hg1[4];
#pragma unroll
        for (int i = 0; i < 4; ++i) {
            int e = e0 + rr + i;
            vsrc[i] = eidx[e];
            vdst[i] = eidx[N_EDGES + e];
        }
#pragma unroll
        for (int i = 0; i < 4; ++i) {
            const float4* hp = (const float4*)(d_z + (size_t)vsrc[i] * HID + cc);
            hg0[i] = hp[0];
            hg1[i] = hp[1];
        }

        float acc[8][4];
#pragma unroll
        for (int nt = 0; nt < 8; ++nt)
#pragma unroll
            for (int j = 0; j < 4; ++j) acc[nt][j] = 0.f;

        // GEMM1: [64x32] @ [32x64]
#pragma unroll
        for (int ks = 0; ks < 4; ++ks) {
            uint32_t a0 = __float_as_uint(sA[(r0 + quad) * SA_E + ks * 8 + tq]);
            uint32_t a1 = __float_as_uint(sA[(r0 + quad + 8) * SA_E + ks * 8 + tq]);
            uint32_t a2 = __float_as_uint(sA[(r0 + quad) * SA_E + ks * 8 + tq + 4]);
            uint32_t a3 = __float_as_uint(sA[(r0 + quad + 8) * SA_E + ks * 8 + tq + 4]);
#pragma unroll
            for (int nt = 0; nt < 8; ++nt) {
                uint32_t b0 = __float_as_uint(sW1[(ks * 8 + tq) * S68 + nt * 8 + quad]);
                uint32_t b1v = __float_as_uint(sW1[(ks * 8 + tq + 4) * S68 + nt * 8 + quad]);
                mma8(acc[nt], a0, a1, a2, a3, b0, b1v);
            }
        }

#pragma unroll
        for (int nt = 0; nt < 8; ++nt) {
            int c = nt * 8 + 2 * tq;
            sH[(r0 + quad) * S68 + c]         = f2tf(fmaxf(acc[nt][0] + sB1[c], 0.f));
            sH[(r0 + quad) * S68 + c + 1]     = f2tf(fmaxf(acc[nt][1] + sB1[c + 1], 0.f));
            sH[(r0 + quad + 8) * S68 + c]     = f2tf(fmaxf(acc[nt][2] + sB1[c], 0.f));
            sH[(r0 + quad + 8) * S68 + c + 1] = f2tf(fmaxf(acc[nt][3] + sB1[c + 1], 0.f));
        }
        __syncwarp();

#pragma unroll
        for (int nt = 0; nt < 8; ++nt)
#pragma unroll
            for (int j = 0; j < 4; ++j) acc[nt][j] = 0.f;

        // GEMM2: [64x64] @ [64x64]  (A = own rows)
#pragma unroll
        for (int ks = 0; ks < 8; ++ks) {
            uint32_t a0 = __float_as_uint(sH[(r0 + quad) * S68 + ks * 8 + tq]);
            uint32_t a1 = __float_as_uint(sH[(r0 + quad + 8) * S68 + ks * 8 + tq]);
            uint32_t a2 = __float_as_uint(sH[(r0 + quad) * S68 + ks * 8 + tq + 4]);
            uint32_t a3 = __float_as_uint(sH[(r0 + quad + 8) * S68 + ks * 8 + tq + 4]);
#pragma unroll
            for (int nt = 0; nt < 8; ++nt) {
                uint32_t b0 = __float_as_uint(sW2[(ks * 8 + tq) * S68 + nt * 8 + quad]);
                uint32_t b1v = __float_as_uint(sW2[(ks * 8 + tq + 4) * S68 + nt * 8 + quad]);
                mma8(acc[nt], a0, a1, a2, a3, b0, b1v);
            }
        }
        __syncwarp();

#pragma unroll
        for (int nt = 0; nt < 8; ++nt) {
            int c = nt * 8 + 2 * tq;
            sH[(r0 + quad) * S68 + c]         = acc[nt][0] + sB2[c];
            sH[(r0 + quad) * S68 + c + 1]     = acc[nt][1] + sB2[c + 1];
            sH[(r0 + quad + 8) * S68 + c]     = acc[nt][2] + sB2[c];
            sH[(r0 + quad + 8) * S68 + c + 1] = acc[nt][3] + sB2[c + 1];
        }
        __syncthreads();

        // epilogue: msg = relu((h_pre) + e), scatter to agg[dst]
#pragma unroll
        for (int i = 0; i < 4; ++i) {
            const float4* ep = (const float4*)(sH + (rr + i) * S68 + cc);
            float4 ev0 = ep[0], ev1 = ep[1];
            float4 m0, m1;
            m0.x = fmaxf(fmaf(hg0[i].x, ax0.x, bx0.x) + ev0.x, 0.f);
            m0.y = fmaxf(fmaf(hg0[i].y, ax0.y, bx0.y) + ev0.y, 0.f);
            m0.z = fmaxf(fmaf(hg0[i].z, ax0.z, bx0.z) + ev0.z, 0.f);
            m0.w = fmaxf(fmaf(hg0[i].w, ax0.w, bx0.w) + ev0.w, 0.f);
            m1.x = fmaxf(fmaf(hg1[i].x, ax1.x, bx1.x) + ev1.x, 0.f);
            m1.y = fmaxf(fmaf(hg1[i].y, ax1.y, bx1.y) + ev1.y, 0.f);
            m1.z = fmaxf(fmaf(hg1[i].z, ax1.z, bx1.z) + ev1.z, 0.f);
            m1.w = fmaxf(fmaf(hg1[i].w, ax1.w, bx1.w) + ev1.w, 0.f);
            red4(d_agg + (size_t)vdst[i] * HID + cc, m0);
            red4(d_agg + (size_t)vdst[i] * HID + cc + 4, m1);
        }
    }
}

// =====================================================================
// Fused node kernel: multi-tile + agg re-zero + last-block BN finalize
// =====================================================================
#define N_SMEM_FLOATS (64*S68 + 64*S68 + 64 + 64 + 64*S68 + 64*S68 + 128)

__global__ __launch_bounds__(128)
void node_kernel(const float* __restrict__ w1, const float* __restrict__ b1,
                 const float* __restrict__ w2, const float* __restrict__ b2,
                 const float* __restrict__ epsp, const float* __restrict__ ab,
                 const float* __restrict__ gamma, const float* __restrict__ beta,
                 int slot) {
    extern __shared__ float smem[];
    float* sW1 = smem;
    float* sW2 = sW1 + 64 * S68;
    float* sB1 = sW2 + 64 * S68;
    float* sB2 = sB1 + 64;
    float* sA  = sB2 + 64;
    float* sH  = sA + 64 * S68;
    float* sSum = sH + 64 * S68;
    float* sSq  = sSum + 64;

    const int tid = threadIdx.x;
    const int lane = tid & 31, warp = tid >> 5;
    const int quad = lane >> 2, tq = lane & 3;
    const int r0 = warp * 16;
    const int tc = tid & 7, tr = tid >> 3;
    const int cc = tc * 8, rr = tr * 4;
    const float epl = 1.f + epsp[0];

    for (int i = tid; i < 1024; i += 128) {
        float4 v = ((const float4*)w1)[i];
        float* d = sW1 + (i >> 4) * S68 + (i & 15) * 4;
        d[0] = f2tf(v.x); d[1] = f2tf(v.y); d[2] = f2tf(v.z); d[3] = f2tf(v.w);
    }
    for (int i = tid; i < 1024; i += 128) {
        float4 v = ((const float4*)w2)[i];
        float* d = sW2 + (i >> 4) * S68 + (i & 15) * 4;
        d[0] = f2tf(v.x); d[1] = f2tf(v.y); d[2] = f2tf(v.z); d[3] = f2tf(v.w);
    }
    if (tid < 64) { sB1[tid] = b1[tid]; sB2[tid] = b2[tid];
                    sSum[tid] = 0.f; sSq[tid] = 0.f; }

    float csum[8], csq[8];
#pragma unroll
    for (int j = 0; j < 8; ++j) { csum[j] = 0.f; csq[j] = 0.f; }

    const float4 zero4 = make_float4(0.f, 0.f, 0.f, 0.f);

    for (int tile = blockIdx.x; tile < N_TILES; tile += N_GRID) {
        const int n0 = tile * 64;

        for (int i = tid; i < 1024; i += 128) {
            int r = i >> 4, q = i & 15;
            int n = n0 + r;
            float4 v = zero4;
            if (n < N_NODES) {
                float4 zv = ((const float4*)(d_z + (size_t)n * HID))[q];
                float4 av = ((const float4*)(d_agg + (size_t)n * HID))[q];
                float4 aa = ((const float4*)ab)[q];
                float4 bb = ((const float4*)(ab + 64))[q];
                v.x = fmaf(zv.x, epl * aa.x, epl * bb.x) + av.x;
                v.y = fmaf(zv.y, epl * aa.y, epl * bb.y) + av.y;
                v.z = fmaf(zv.z, epl * aa.z, epl * bb.z) + av.z;
                v.w = fmaf(zv.w, epl * aa.w, epl * bb.w) + av.w;
                // re-zero agg for next layer (fused memset)
                ((float4*)(d_agg + (size_t)n * HID))[q] = zero4;
            }
            float* d = sA + r * S68 + q * 4;
            d[0] = f2tf(v.x); d[1] = f2tf(v.y); d[2] = f2tf(v.z); d[3] = f2tf(v.w);
        }
        __syncthreads();

        float acc[8][4];
#pragma unroll
        for (int nt = 0; nt < 8; ++nt)
#pragma unroll
            for (int j = 0; j < 4; ++j) acc[nt][j] = 0.f;

#pragma unroll
        for (int ks = 0; ks < 8; ++ks) {
            uint32_t a0 = __float_as_uint(sA[(r0 + quad) * S68 + ks * 8 + tq]);
            uint32_t a1 = __float_as_uint(sA[(r0 + quad + 8) * S68 + ks * 8 + tq]);
            uint32_t a2 = __float_as_uint(sA[(r0 + quad) * S68 + ks * 8 + tq + 4]);
            uint32_t a3 = __float_as_uint(sA[(r0 + quad + 8) * S68 + ks * 8 + tq + 4]);
#pragma unroll
            for (int nt = 0; nt < 8; ++nt) {
                uint32_t b0 = __float_as_uint(sW1[(ks * 8 + tq) * S68 + nt * 8 + quad]);
                uint32_t b1v = __float_as_uint(sW1[(ks * 8 + tq + 4) * S68 + nt * 8 + quad]);
                mma8(acc[nt], a0, a1, a2, a3, b0, b1v);
            }
        }

#pragma unroll
        for (int nt = 0; nt < 8; ++nt) {
            int c = nt * 8 + 2 * tq;
            sH[(r0 + quad) * S68 + c]         = f2tf(fmaxf(acc[nt][0] + sB1[c], 0.f));
            sH[(r0 + quad) * S68 + c + 1]     = f2tf(fmaxf(acc[nt][1] + sB1[c + 1], 0.f));
            sH[(r0 + quad + 8) * S68 + c]     = f2tf(fmaxf(acc[nt][2] + sB1[c], 0.f));
            sH[(r0 + quad + 8) * S68 + c + 1] = f2tf(fmaxf(acc[nt][3] + sB1[c + 1], 0.f));
        }
        __syncwarp();

#pragma unroll
        for (int nt = 0; nt < 8; ++nt)
#pragma unroll
            for (int j = 0; j < 4; ++j) acc[nt][j] = 0.f;

#pragma unroll
        for (int ks = 0; ks < 8; ++ks) {
            uint32_t a0 = __float_as_uint(sH[(r0 + quad) * S68 + ks * 8 + tq]);
            uint32_t a1 = __float_as_uint(sH[(r0 + quad + 8) * S68 + ks * 8 + tq]);
            uint32_t a2 = __float_as_uint(sH[(r0 + quad) * S68 + ks * 8 + tq + 4]);
            uint32_t a3 = __float_as_uint(sH[(r0 + quad + 8) * S68 + ks * 8 + tq + 4]);
#pragma unroll
            for (int nt = 0; nt < 8; ++nt) {
                uint32_t b0 = __float_as_uint(sW2[(ks * 8 + tq) * S68 + nt * 8 + quad]);
                uint32_t b1v = __float_as_uint(sW2[(ks * 8 + tq + 4) * S68 + nt * 8 + quad]);
                mma8(acc[nt], a0, a1, a2, a3, b0, b1v);
            }
        }
        __syncwarp();

#pragma unroll
        for (int nt = 0; nt < 8; ++nt) {
            int c = nt * 8 + 2 * tq;
            sH[(r0 + quad) * S68 + c]         = acc[nt][0] + sB2[c];
            sH[(r0 + quad) * S68 + c + 1]     = acc[nt][1] + sB2[c + 1];
            sH[(r0 + quad + 8) * S68 + c]     = acc[nt][2] + sB2[c];
            sH[(r0 + quad + 8) * S68 + c + 1] = acc[nt][3] + sB2[c + 1];
        }
        __syncthreads();

#pragma unroll
        for (int i = 0; i < 4; ++i) {
            int n = n0 + rr + i;
            if (n < N_NODES) {
                const float* ev = sH + (rr + i) * S68 + cc;
                float zv[8];
#pragma unroll
                for (int j = 0; j < 8; ++j) {
                    zv[j] = fmaxf(ev[j], 0.f);
                    csum[j] += zv[j];
                    csq[j] += zv[j] * zv[j];
                }
                float4* zp = (float4*)(d_z + (size_t)n * HID + cc);
                zp[0] = make_float4(zv[0], zv[1], zv[2], zv[3]);
                zp[1] = make_float4(zv[4], zv[5], zv[6], zv[7]);
            }
        }
    }

    __syncthreads();
#pragma unroll
    for (int j = 0; j < 8; ++j) {
        atomicAdd(&sSum[cc + j], csum[j]);
        atomicAdd(&sSq[cc + j], csq[j]);
    }
    __syncthreads();
    if (tid < 64) {
        atomicAdd(&d_bnsum[tid], sSum[tid]);
        atomicAdd(&d_bnsum[64 + tid], sSq[tid]);
    }

    // ---- last block computes AB and resets bnsum ----
    __threadfence();
    __shared__ int isLast;
    if (tid == 0) isLast = (atomicAdd(&d_ncount, 1) == N_GRID - 1);
    __syncthreads();
    if (isLast) {
        if (tid < 64) {
            float mu = d_bnsum[tid] / (float)N_NODES;
            float var = d_bnsum[64 + tid] / (float)N_NODES - mu * mu;
            float a = gamma[tid] * rsqrtf(var + BN_EPS);
            d_bnABL[slot * 128 + tid] = a;
            d_bnABL[slot * 128 + 64 + tid] = beta[tid] - mu * a;
            d_bnsum[tid] = 0.f;
            d_bnsum[64 + tid] = 0.f;
        }
        if (tid == 0) d_ncount = 0;
    }
}

// ---------- pool: o = z*a+b, block pre-reduction, scatter ----------
__global__ __launch_bounds__(256)
void pool_kernel(int layer, const int* __restrict__ batch,
                 const float* __restrict__ ab) {
    __shared__ float4 sm4[256];
    __shared__ int sg[2];
    const int tid = threadIdx.x;
    const int i = blockIdx.x * 256 + tid;
    const int c4 = i & 15;
    const int node = i >> 4;

    float4 z = ((const float4*)d_z)[i];
    float4 a = ((const float4*)ab)[c4];
    float4 b = ((const float4*)(ab + 64))[c4];
    float4 o;
    o.x = fmaf(z.x, a.x, b.x);
    o.y = fmaf(z.y, a.y, b.y);
    o.z = fmaf(z.z, a.z, b.z);
    o.w = fmaf(z.w, a.w, b.w);

    const int nfirst = (blockIdx.x * 256) >> 4;
    if (tid == 0) { sg[0] = batch[nfirst]; sg[1] = batch[nfirst + 15]; }
    __syncthreads();

    if (sg[0] == sg[1]) {
        sm4[tid] = o;
        __syncthreads();
#pragma unroll
        for (int s = 128; s >= 16; s >>= 1) {
            if (tid < s) {
                float4 u = sm4[tid + s];
                float4 w = sm4[tid];
                w.x += u.x; w.y += u.y; w.z += u.z; w.w += u.w;
                sm4[tid] = w;
            }
            __syncthreads();
        }
        if (tid < 16)
            red4(d_gsum + (size_t)sg[0] * (L_LAYERS * HID) + layer * HID + tid * 4,
                 sm4[tid]);
        if (layer == 0 && tid == 0) atomicAdd(&d_gcnt[sg[0]], 16.0f);
    } else {
        int g = batch[node];
        red4(d_gsum + (size_t)g * (L_LAYERS * HID) + layer * HID + c4 * 4, o);
        if (layer == 0 && c4 == 0) atomicAdd(&d_gcnt[g], 1.0f);
    }
}

// ---------------- per-graph fc0 + weighted scatter ----------------
__global__ __launch_bounds__(64)
void graph_kernel(const float* __restrict__ fc0w, const float* __restrict__ fc0b,
                  const float* __restrict__ gweights, const int* __restrict__ subb) {
    __shared__ float sG[192];
    int g = blockIdx.x;
    int c = threadIdx.x;
    float inv = 1.f / fmaxf(d_gcnt[g], 1.f);
    for (int i = c; i < 192; i += 64) sG[i] = d_gsum[(size_t)g * 192 + i] * inv;
    __syncthreads();
    float acc = fc0b[c];
    for (int k = 0; k < 192; ++k) acc += sG[k] * fc0w[k * 64 + c];
    float w = gweights[g];
    float v = fmaxf(acc, 0.f) * w;
    int s = subb[g];
    atomicAdd(&d_svec[s * 64 + c], v);
    if (c == 0) atomicAdd(&d_snorm[s], w);
}

// ---------------- subgraph FC layers ----------------
__global__ __launch_bounds__(64)
void fc_kernel(const float* __restrict__ w, const float* __restrict__ b,
               const float* __restrict__ in, float* __restrict__ out,
               int normalize) {
    __shared__ float sR[64];
    int row = blockIdx.x;
    int c = threadIdx.x;
    float v = in[row * 64 + c];
    if (normalize) v = v / fmaxf(d_snorm[row], 1e-12f);
    sR[c] = v;
    __syncthreads();
    float acc = b[c];
    for (int k = 0; k < 64; ++k) acc += sR[k] * w[k * 64 + c];
    out[row * 64 + c] = fmaxf(acc, 0.f);
}

__global__ __launch_bounds__(32)
void pred_kernel(const float* __restrict__ w, const float* __restrict__ b,
                 const float* __restrict__ in, float* __restrict__ out) {
    __shared__ float sR[64];
    int row = blockIdx.x;
    int c = threadIdx.x;
    sR[c] = in[row * 64 + c];
    sR[c + 32] = in[row * 64 + c + 32];
    __syncthreads();
    float acc = b[c];
    for (int k = 0; k < 64; ++k) acc += sR[k] * w[k * 32 + c];
    out[row * 32 + c] = acc;
}

// =====================================================================
extern "C" void kernel_launch(void* const* d_in, const int* in_sizes, int n_in,
                              void* d_out, int out_size) {
    const float* x       = (const float*)d_in[0];
    const int*   eidx    = (const int*)d_in[1];
    const float* eattr   = (const float*)d_in[2];
    const int*   batch   = (const int*)d_in[3];
    const float* weights = (const float*)d_in[4];
    const int*   subb    = (const int*)d_in[5];
    const float* be_w1   = (const float*)d_in[6];
    const float* be_b1   = (const float*)d_in[7];
    const float* be_w2   = (const float*)d_in[8];
    const float* be_b2   = (const float*)d_in[9];
    const float* mlp_w1  = (const float*)d_in[10];
    const float* mlp_b1  = (const float*)d_in[11];
    const float* mlp_w2  = (const float*)d_in[12];
    const float* mlp_b2  = (const float*)d_in[13];
    const float* epsv    = (const float*)d_in[14];
    const float* bn_g    = (const float*)d_in[15];
    const float* bn_b    = (const float*)d_in[16];
    const float* fc0_w   = (const float*)d_in[17];
    const float* fc0_b   = (const float*)d_in[18];
    const float* fc1_w   = (const float*)d_in[19];
    const float* fc1_b   = (const float*)d_in[20];
    const float* fc2_w   = (const float*)d_in[21];
    const float* fc2_b   = (const float*)d_in[22];
    const float* pred_w  = (const float*)d_in[23];
    const float* pred_b  = (const float*)d_in[24];
    float* out = (float*)d_out;

    void *p_z, *p_agg, *p_abl, *p_gsum, *p_gcnt, *p_svec, *p_snorm, *p_t1, *p_t2;
    cudaGetSymbolAddress(&p_z, d_z);
    cudaGetSymbolAddress(&p_agg, d_agg);
    cudaGetSymbolAddress(&p_abl, d_bnABL);
    cudaGetSymbolAddress(&p_gsum, d_gsum);
    cudaGetSymbolAddress(&p_gcnt, d_gcnt);
    cudaGetSymbolAddress(&p_svec, d_svec);
    cudaGetSymbolAddress(&p_snorm, d_snorm);
    cudaGetSymbolAddress(&p_t1, d_t1);
    cudaGetSymbolAddress(&p_t2, d_t2);
    const float* abl = (const float*)p_abl;

    cudaFuncSetAttribute(edge_kernel, cudaFuncAttributeMaxDynamicSharedMemorySize,
                         E_SMEM_FLOATS * (int)sizeof(float));
    cudaFuncSetAttribute(node_kernel, cudaFuncAttributeMaxDynamicSharedMemorySize,
                         N_SMEM_FLOATS * (int)sizeof(float));

    cudaMemcpyAsync(p_z, x, (size_t)N_NODES * HID * sizeof(float),
                    cudaMemcpyDeviceToDevice);
    init_ab<<<1, 64>>>();
    cudaMemsetAsync(p_agg, 0, (size_t)N_NODES * HID * sizeof(float));
    cudaMemsetAsync(p_gsum, 0, (size_t)G_GRAPHS * 192 * sizeof(float));
    cudaMemsetAsync(p_gcnt, 0, G_GRAPHS * sizeof(float));
    cudaMemsetAsync(p_svec, 0, S_SUB * HID * sizeof(float));
    cudaMemsetAsync(p_snorm, 0, S_SUB * sizeof(float));

    for (int l = 0; l < L_LAYERS; ++l) {
        edge_kernel<<<E_GRID, 128, E_SMEM_FLOATS * sizeof(float)>>>(
            eattr, eidx,
            be_w1 + l * EDGE_F * HID, be_b1 + l * HID,
            be_w2 + l * HID * HID,    be_b2 + l * HID,
            abl + l * 128);

        node_kernel<<<N_GRID, 128, N_SMEM_FLOATS * sizeof(float)>>>(
            mlp_w1 + l * HID * HID, mlp_b1 + l * HID,
            mlp_w2 + l * HID * HID, mlp_b2 + l * HID,
            epsv + l, abl + l * 128,
            bn_g + l * HID, bn_b + l * HID, l + 1);

        pool_kernel<<<(N_NODES * 16) / 256, 256>>>(l, batch, abl + (l + 1) * 128);
    }

    graph_kernel<<<G_GRAPHS, 64>>>(fc0_w, fc0_b, weights, subb);
    fc_kernel<<<S_SUB, 64>>>(fc1_w, fc1_b, (const float*)p_svec, (float*)p_t1, 1);
    fc_kernel<<<S_SUB, 64>>>(fc2_w, fc2_b, (const float*)p_t1, (float*)p_t2, 0);
    pred_kernel<<<S_SUB, 32>>>(pred_w, pred_b, (const float*)p_t2, out);
}

// round 9
// speedup vs baseline: 1.1178x; 1.1178x over previous
#include <cuda_runtime.h>
#include <cstddef>
#include <cstdint>

#define N_NODES 100000
#define N_EDGES 1000000
#define G_GRAPHS 1024
#define S_SUB 128
#define HID 64
#define EDGE_F 32
#define OUT_F 32
#define L_LAYERS 3
#define BN_EPS 1e-5f

#define E_TILES_TOTAL 15625
#define E_GRID 2048
#define N_TILES 1563
#define N_GRID 512

// ---------------- device scratch ----------------
__device__ float d_z[N_NODES * HID];
__device__ float d_agg[N_NODES * HID];
__device__ float d_bnsum[L_LAYERS * 2 * HID];   // per-layer slots
__device__ float d_gsum[G_GRAPHS * L_LAYERS * HID];
__device__ float d_gcnt[G_GRAPHS];
__device__ float d_svec[S_SUB * HID];
__device__ float d_snorm[S_SUB];
__device__ float d_t1[S_SUB * HID];
__device__ float d_t2[S_SUB * HID];

__device__ __forceinline__ void red4(float* addr, float4 v) {
    asm volatile("red.global.add.v4.f32 [%0], {%1,%2,%3,%4};"
                 :: "l"(addr), "f"(v.x), "f"(v.y), "f"(v.z), "f"(v.w)
                 : "memory");
}

__device__ __forceinline__ float f2tf(float x) {
    uint32_t r;
    asm("cvt.rna.tf32.f32 %0, %1;" : "=r"(r) : "f"(x));
    return __uint_as_float(r);
}

__device__ __forceinline__ void mma8(float* d, uint32_t a0, uint32_t a1,
                                     uint32_t a2, uint32_t a3,
                                     uint32_t b0, uint32_t b1) {
    asm volatile(
        "mma.sync.aligned.m16n8k8.row.col.f32.tf32.tf32.f32 "
        "{%0,%1,%2,%3}, {%4,%5,%6,%7}, {%8,%9}, {%0,%1,%2,%3};"
        : "+f"(d[0]), "+f"(d[1]), "+f"(d[2]), "+f"(d[3])
        : "r"(a0), "r"(a1), "r"(a2), "r"(a3), "r"(b0), "r"(b1));
}

#define SA_E 36
#define S68 68

// ---------------- one-time graph node counts ----------------
__global__ void count_kernel(const int* __restrict__ batch) {
    int i = blockIdx.x * 256 + threadIdx.x;
    if (i < N_NODES) atomicAdd(&d_gcnt[batch[i]], 1.0f);
}

// =====================================================================
// Fused edge kernel (round-5 structure + inline BN affine)
// =====================================================================
#define E_SMEM_FLOATS (32*S68 + 64*S68 + 64 + 64 + 64*SA_E + 64*S68 + 128)

__global__ __launch_bounds__(128)
void edge_kernel(const float* __restrict__ edge_attr,
                 const int* __restrict__ eidx,
                 const float* __restrict__ w1, const float* __restrict__ b1,
                 const float* __restrict__ w2, const float* __restrict__ b2,
                 const float* __restrict__ bnsum_prev,
                 const float* __restrict__ gamma_prev,
                 const float* __restrict__ beta_prev, int useBN) {
    extern __shared__ float smem[];
    float* sW1 = smem;                    // [32][68] tf32
    float* sW2 = sW1 + 32 * S68;          // [64][68] tf32
    float* sB1 = sW2 + 64 * S68;
    float* sB2 = sB1 + 64;
    float* sA  = sB2 + 64;                // [64][36]
    float* sH  = sA + 64 * SA_E;          // [64][68]
    float* sAB = sH + 64 * S68;           // [128] affine a|b

    const int tid = threadIdx.x;
    const int lane = tid & 31, warp = tid >> 5;
    const int quad = lane >> 2, tq = lane & 3;
    const int r0 = warp * 16;
    const int tc = tid & 7, tr = tid >> 3;
    const int cc = tc * 8, rr = tr * 4;

    for (int i = tid; i < 512; i += 128) {
        float4 v = ((const float4*)w1)[i];
        float* d = sW1 + (i >> 4) * S68 + (i & 15) * 4;
        d[0] = f2tf(v.x); d[1] = f2tf(v.y); d[2] = f2tf(v.z); d[3] = f2tf(v.w);
    }
    for (int i = tid; i < 1024; i += 128) {
        float4 v = ((const float4*)w2)[i];
        float* d = sW2 + (i >> 4) * S68 + (i & 15) * 4;
        d[0] = f2tf(v.x); d[1] = f2tf(v.y); d[2] = f2tf(v.z); d[3] = f2tf(v.w);
    }
    if (tid < 64) {
        sB1[tid] = b1[tid]; sB2[tid] = b2[tid];
        float a = 1.f, b = 0.f;
        if (useBN) {
            float mu = bnsum_prev[tid] * (1.f / (float)N_NODES);
            float var = bnsum_prev[64 + tid] * (1.f / (float)N_NODES) - mu * mu;
            a = gamma_prev[tid] * rsqrtf(var + BN_EPS);
            b = beta_prev[tid] - mu * a;
        }
        sAB[tid] = a; sAB[64 + tid] = b;
    }
    __syncthreads();

    const float4 ax0 = *((const float4*)(sAB + cc));
    const float4 ax1 = *((const float4*)(sAB + cc + 4));
    const float4 bx0 = *((const float4*)(sAB + 64 + cc));
    const float4 bx1 = *((const float4*)(sAB + 64 + cc + 4));

    for (int tile = blockIdx.x; tile < E_TILES_TOTAL; tile += E_GRID) {
        const int e0 = tile * 64;

        for (int i = tid; i < 512; i += 128) {
            int r = i >> 3, q = i & 7;
            float4 v = ((const float4*)(edge_attr + (size_t)(e0 + r) * EDGE_F))[q];
            float* d = sA + r * SA_E + q * 4;
            d[0] = f2tf(v.x); d[1] = f2tf(v.y); d[2] = f2tf(v.z); d[3] = f2tf(v.w);
        }
        __syncthreads();

        float acc[8][4];
#pragma unroll
        for (int nt = 0; nt < 8; ++nt)
#pragma unroll
            for (int j = 0; j < 4; ++j) acc[nt][j] = 0.f;

        // GEMM1: [64x32] @ [32x64]
#pragma unroll
        for (int ks = 0; ks < 4; ++ks) {
            uint32_t a0 = __float_as_uint(sA[(r0 + quad) * SA_E + ks * 8 + tq]);
            uint32_t a1 = __float_as_uint(sA[(r0 + quad + 8) * SA_E + ks * 8 + tq]);
            uint32_t a2 = __float_as_uint(sA[(r0 + quad) * SA_E + ks * 8 + tq + 4]);
            uint32_t a3 = __float_as_uint(sA[(r0 + quad + 8) * SA_E + ks * 8 + tq + 4]);
#pragma unroll
            for (int nt = 0; nt < 8; ++nt) {
                uint32_t b0 = __float_as_uint(sW1[(ks * 8 + tq) * S68 + nt * 8 + quad]);
                uint32_t b1v = __float_as_uint(sW1[(ks * 8 + tq + 4) * S68 + nt * 8 + quad]);
                mma8(acc[nt], a0, a1, a2, a3, b0, b1v);
            }
        }

#pragma unroll
        for (int nt = 0; nt < 8; ++nt) {
            int c = nt * 8 + 2 * tq;
            sH[(r0 + quad) * S68 + c]         = f2tf(fmaxf(acc[nt][0] + sB1[c], 0.f));
            sH[(r0 + quad) * S68 + c + 1]     = f2tf(fmaxf(acc[nt][1] + sB1[c + 1], 0.f));
            sH[(r0 + quad + 8) * S68 + c]     = f2tf(fmaxf(acc[nt][2] + sB1[c], 0.f));
            sH[(r0 + quad + 8) * S68 + c + 1] = f2tf(fmaxf(acc[nt][3] + sB1[c + 1], 0.f));
        }
        __syncwarp();

#pragma unroll
        for (int nt = 0; nt < 8; ++nt)
#pragma unroll
            for (int j = 0; j < 4; ++j) acc[nt][j] = 0.f;

        // GEMM2: [64x64] @ [64x64]
#pragma unroll
        for (int ks = 0; ks < 8; ++ks) {
            uint32_t a0 = __float_as_uint(sH[(r0 + quad) * S68 + ks * 8 + tq]);
            uint32_t a1 = __float_as_uint(sH[(r0 + quad + 8) * S68 + ks * 8 + tq]);
            uint32_t a2 = __float_as_uint(sH[(r0 + quad) * S68 + ks * 8 + tq + 4]);
            uint32_t a3 = __float_as_uint(sH[(r0 + quad + 8) * S68 + ks * 8 + tq + 4]);
#pragma unroll
            for (int nt = 0; nt < 8; ++nt) {
                uint32_t b0 = __float_as_uint(sW2[(ks * 8 + tq) * S68 + nt * 8 + quad]);
                uint32_t b1v = __float_as_uint(sW2[(ks * 8 + tq + 4) * S68 + nt * 8 + quad]);
                mma8(acc[nt], a0, a1, a2, a3, b0, b1v);
            }
        }
        __syncwarp();

#pragma unroll
        for (int nt = 0; nt < 8; ++nt) {
            int c = nt * 8 + 2 * tq;
            sH[(r0 + quad) * S68 + c]         = acc[nt][0] + sB2[c];
            sH[(r0 + quad) * S68 + c + 1]     = acc[nt][1] + sB2[c + 1];
            sH[(r0 + quad + 8) * S68 + c]     = acc[nt][2] + sB2[c];
            sH[(r0 + quad + 8) * S68 + c + 1] = acc[nt][3] + sB2[c + 1];
        }
        __syncthreads();

        // epilogue: msg = relu((z[src]*a+b) + e), scatter to agg[dst]
#pragma unroll
        for (int i = 0; i < 4; ++i) {
            int e = e0 + rr + i;
            int src = eidx[e];
            int dst = eidx[N_EDGES + e];
            const float4* hp = (const float4*)(d_z + (size_t)src * HID + cc);
            float4 h0 = hp[0], h1 = hp[1];
            const float4* ep = (const float4*)(sH + (rr + i) * S68 + cc);
            float4 ev0 = ep[0], ev1 = ep[1];
            float4 m0, m1;
            m0.x = fmaxf(fmaf(h0.x, ax0.x, bx0.x) + ev0.x, 0.f);
            m0.y = fmaxf(fmaf(h0.y, ax0.y, bx0.y) + ev0.y, 0.f);
            m0.z = fmaxf(fmaf(h0.z, ax0.z, bx0.z) + ev0.z, 0.f);
            m0.w = fmaxf(fmaf(h0.w, ax0.w, bx0.w) + ev0.w, 0.f);
            m1.x = fmaxf(fmaf(h1.x, ax1.x, bx1.x) + ev1.x, 0.f);
            m1.y = fmaxf(fmaf(h1.y, ax1.y, bx1.y) + ev1.y, 0.f);
            m1.z = fmaxf(fmaf(h1.z, ax1.z, bx1.z) + ev1.z, 0.f);
            m1.w = fmaxf(fmaf(h1.w, ax1.w, bx1.w) + ev1.w, 0.f);
            red4(d_agg + (size_t)dst * HID + cc, m0);
            red4(d_agg + (size_t)dst * HID + cc + 4, m1);
        }
    }
}

// =====================================================================
// Fused node kernel: MLP + BN stats + fused graph-pool scatter (raw z)
// =====================================================================
#define N_SMEM_FLOATS (64*S68 + 64*S68 + 64 + 64 + 64*S68 + 64*S68 + 128 + 128)

__global__ __launch_bounds__(128)
void node_kernel(const float* __restrict__ w1, const float* __restrict__ b1,
                 const float* __restrict__ w2, const float* __restrict__ b2,
                 const float* __restrict__ epsp,
                 const float* __restrict__ bnsum_prev,
                 const float* __restrict__ gamma_prev,
                 const float* __restrict__ beta_prev, int useBN,
                 int layer, const int* __restrict__ batch) {
    extern __shared__ float smem[];
    float* sW1 = smem;
    float* sW2 = sW1 + 64 * S68;
    float* sB1 = sW2 + 64 * S68;
    float* sB2 = sB1 + 64;
    float* sA  = sB2 + 64;
    float* sH  = sA + 64 * S68;
    float* sSum = sH + 64 * S68;          // [64]
    float* sSq  = sSum + 64;              // [64]
    float* sAB  = sSq + 64;               // [128]

    const int tid = threadIdx.x;
    const int lane = tid & 31, warp = tid >> 5;
    const int quad = lane >> 2, tq = lane & 3;
    const int r0 = warp * 16;
    const int tc = tid & 7, tr = tid >> 3;
    const int cc = tc * 8, rr = tr * 4;
    const float epl = 1.f + epsp[0];

    for (int i = tid; i < 1024; i += 128) {
        float4 v = ((const float4*)w1)[i];
        float* d = sW1 + (i >> 4) * S68 + (i & 15) * 4;
        d[0] = f2tf(v.x); d[1] = f2tf(v.y); d[2] = f2tf(v.z); d[3] = f2tf(v.w);
    }
    for (int i = tid; i < 1024; i += 128) {
        float4 v = ((const float4*)w2)[i];
        float* d = sW2 + (i >> 4) * S68 + (i & 15) * 4;
        d[0] = f2tf(v.x); d[1] = f2tf(v.y); d[2] = f2tf(v.z); d[3] = f2tf(v.w);
    }
    if (tid < 64) {
        sB1[tid] = b1[tid]; sB2[tid] = b2[tid];
        sSum[tid] = 0.f; sSq[tid] = 0.f;
        float a = 1.f, b = 0.f;
        if (useBN) {
            float mu = bnsum_prev[tid] * (1.f / (float)N_NODES);
            float var = bnsum_prev[64 + tid] * (1.f / (float)N_NODES) - mu * mu;
            a = gamma_prev[tid] * rsqrtf(var + BN_EPS);
            b = beta_prev[tid] - mu * a;
        }
        sAB[tid] = a; sAB[64 + tid] = b;
    }
    __syncthreads();   // *** THE FIX: sAB must be visible before first tile ***

    float csum[8], csq[8];
#pragma unroll
    for (int j = 0; j < 8; ++j) { csum[j] = 0.f; csq[j] = 0.f; }

    for (int tile = blockIdx.x; tile < N_TILES; tile += N_GRID) {
        const int n0 = tile * 64;

        for (int i = tid; i < 1024; i += 128) {
            int r = i >> 4, q = i & 15;
            int n = n0 + r;
            float4 v = make_float4(0.f, 0.f, 0.f, 0.f);
            if (n < N_NODES) {
                float4 zv = ((const float4*)(d_z + (size_t)n * HID))[q];
                float4 av = ((const float4*)(d_agg + (size_t)n * HID))[q];
                float4 aa = ((const float4*)sAB)[q];
                float4 bb = ((const float4*)(sAB + 64))[q];
                v.x = fmaf(zv.x, epl * aa.x, epl * bb.x) + av.x;
                v.y = fmaf(zv.y, epl * aa.y, epl * bb.y) + av.y;
                v.z = fmaf(zv.z, epl * aa.z, epl * bb.z) + av.z;
                v.w = fmaf(zv.w, epl * aa.w, epl * bb.w) + av.w;
            }
            float* d = sA + r * S68 + q * 4;
            d[0] = f2tf(v.x); d[1] = f2tf(v.y); d[2] = f2tf(v.z); d[3] = f2tf(v.w);
        }
        __syncthreads();

        float acc[8][4];
#pragma unroll
        for (int nt = 0; nt < 8; ++nt)
#pragma unroll
            for (int j = 0; j < 4; ++j) acc[nt][j] = 0.f;

#pragma unroll
        for (int ks = 0; ks < 8; ++ks) {
            uint32_t a0 = __float_as_uint(sA[(r0 + quad) * S68 + ks * 8 + tq]);
            uint32_t a1 = __float_as_uint(sA[(r0 + quad + 8) * S68 + ks * 8 + tq]);
            uint32_t a2 = __float_as_uint(sA[(r0 + quad) * S68 + ks * 8 + tq + 4]);
            uint32_t a3 = __float_as_uint(sA[(r0 + quad + 8) * S68 + ks * 8 + tq + 4]);
#pragma unroll
            for (int nt = 0; nt < 8; ++nt) {
                uint32_t b0 = __float_as_uint(sW1[(ks * 8 + tq) * S68 + nt * 8 + quad]);
                uint32_t b1v = __float_as_uint(sW1[(ks * 8 + tq + 4) * S68 + nt * 8 + quad]);
                mma8(acc[nt], a0, a1, a2, a3, b0, b1v);
            }
        }

#pragma unroll
        for (int nt = 0; nt < 8; ++nt) {
            int c = nt * 8 + 2 * tq;
            sH[(r0 + quad) * S68 + c]         = f2tf(fmaxf(acc[nt][0] + sB1[c], 0.f));
            sH[(r0 + quad) * S68 + c + 1]     = f2tf(fmaxf(acc[nt][1] + sB1[c + 1], 0.f));
            sH[(r0 + quad + 8) * S68 + c]     = f2tf(fmaxf(acc[nt][2] + sB1[c], 0.f));
            sH[(r0 + quad + 8) * S68 + c + 1] = f2tf(fmaxf(acc[nt][3] + sB1[c + 1], 0.f));
        }
        __syncwarp();

#pragma unroll
        for (int nt = 0; nt < 8; ++nt)
#pragma unroll
            for (int j = 0; j < 4; ++j) acc[nt][j] = 0.f;

#pragma unroll
        for (int ks = 0; ks < 8; ++ks) {
            uint32_t a0 = __float_as_uint(sH[(r0 + quad) * S68 + ks * 8 + tq]);
            uint32_t a1 = __float_as_uint(sH[(r0 + quad + 8) * S68 + ks * 8 + tq]);
            uint32_t a2 = __float_as_uint(sH[(r0 + quad) * S68 + ks * 8 + tq + 4]);
            uint32_t a3 = __float_as_uint(sH[(r0 + quad + 8) * S68 + ks * 8 + tq + 4]);
#pragma unroll
            for (int nt = 0; nt < 8; ++nt) {
                uint32_t b0 = __float_as_uint(sW2[(ks * 8 + tq) * S68 + nt * 8 + quad]);
                uint32_t b1v = __float_as_uint(sW2[(ks * 8 + tq + 4) * S68 + nt * 8 + quad]);
                mma8(acc[nt], a0, a1, a2, a3, b0, b1v);
            }
        }
        __syncwarp();

#pragma unroll
        for (int nt = 0; nt < 8; ++nt) {
            int c = nt * 8 + 2 * tq;
            sH[(r0 + quad) * S68 + c]         = acc[nt][0] + sB2[c];
            sH[(r0 + quad) * S68 + c + 1]     = acc[nt][1] + sB2[c + 1];
            sH[(r0 + quad + 8) * S68 + c]     = acc[nt][2] + sB2[c];
            sH[(r0 + quad + 8) * S68 + c + 1] = acc[nt][3] + sB2[c + 1];
        }
        __syncthreads();

        // epilogue: relu, write z, BN sums, run-reduced graph-pool scatter
        float racc[8];
#pragma unroll
        for (int j = 0; j < 8; ++j) racc[j] = 0.f;
        int curg = -1;

#pragma unroll
        for (int i = 0; i < 4; ++i) {
            int n = n0 + rr + i;
            if (n < N_NODES) {
                int g = batch[n];
                if (g != curg) {
                    if (curg >= 0) {
                        float* gp = d_gsum + (size_t)curg * (L_LAYERS * HID)
                                    + layer * HID + cc;
                        red4(gp, make_float4(racc[0], racc[1], racc[2], racc[3]));
                        red4(gp + 4, make_float4(racc[4], racc[5], racc[6], racc[7]));
#pragma unroll
                        for (int j = 0; j < 8; ++j) racc[j] = 0.f;
                    }
                    curg = g;
                }
                const float* ev = sH + (rr + i) * S68 + cc;
                float zv[8];
#pragma unroll
                for (int j = 0; j < 8; ++j) {
                    zv[j] = fmaxf(ev[j], 0.f);
                    csum[j] += zv[j];
                    csq[j] += zv[j] * zv[j];
                    racc[j] += zv[j];
                }
                float4* zp = (float4*)(d_z + (size_t)n * HID + cc);
                zp[0] = make_float4(zv[0], zv[1], zv[2], zv[3]);
                zp[1] = make_float4(zv[4], zv[5], zv[6], zv[7]);
            }
        }
        if (curg >= 0) {
            float* gp = d_gsum + (size_t)curg * (L_LAYERS * HID) + layer * HID + cc;
            red4(gp, make_float4(racc[0], racc[1], racc[2], racc[3]));
            red4(gp + 4, make_float4(racc[4], racc[5], racc[6], racc[7]));
        }
    }

    __syncthreads();
#pragma unroll
    for (int j = 0; j < 8; ++j) {
        atomicAdd(&sSum[cc + j], csum[j]);
        atomicAdd(&sSq[cc + j], csq[j]);
    }
    __syncthreads();
    if (tid < 64) {
        atomicAdd(&d_bnsum[layer * 128 + tid], sSum[tid]);
        atomicAdd(&d_bnsum[layer * 128 + 64 + tid], sSq[tid]);
    }
}

// ---------------- per-graph fc0 (+inline BN affine) + scatter ----------------
__global__ __launch_bounds__(64)
void graph_kernel(const float* __restrict__ fc0w, const float* __restrict__ fc0b,
                  const float* __restrict__ gweights, const int* __restrict__ subb,
                  const float* __restrict__ bn_g, const float* __restrict__ bn_b) {
    __shared__ float sG[192];
    __shared__ float sAB[2 * 192];
    int g = blockIdx.x;
    int c = threadIdx.x;

    for (int l = 0; l < L_LAYERS; ++l) {
        float mu = d_bnsum[l * 128 + c] * (1.f / (float)N_NODES);
        float var = d_bnsum[l * 128 + 64 + c] * (1.f / (float)N_NODES) - mu * mu;
        float a = bn_g[l * 64 + c] * rsqrtf(var + BN_EPS);
        sAB[l * 64 + c] = a;
        sAB[192 + l * 64 + c] = bn_b[l * 64 + c] - mu * a;
    }
    __syncthreads();

    float inv = 1.f / fmaxf(d_gcnt[g], 1.f);
    for (int i = c; i < 192; i += 64)
        sG[i] = fmaf(d_gsum[(size_t)g * 192 + i] * inv, sAB[i], sAB[192 + i]);
    __syncthreads();

    float acc = fc0b[c];
    for (int k = 0; k < 192; ++k) acc += sG[k] * fc0w[k * 64 + c];
    float w = gweights[g];
    float v = fmaxf(acc, 0.f) * w;
    int s = subb[g];
    atomicAdd(&d_svec[s * 64 + c], v);
    if (c == 0) atomicAdd(&d_snorm[s], w);
}

// ---------------- subgraph FC layers ----------------
__global__ __launch_bounds__(64)
void fc_kernel(const float* __restrict__ w, const float* __restrict__ b,
               const float* __restrict__ in, float* __restrict__ out,
               int normalize) {
    __shared__ float sR[64];
    int row = blockIdx.x;
    int c = threadIdx.x;
    float v = in[row * 64 + c];
    if (normalize) v = v / fmaxf(d_snorm[row], 1e-12f);
    sR[c] = v;
    __syncthreads();
    float acc = b[c];
    for (int k = 0; k < 64; ++k) acc += sR[k] * w[k * 64 + c];
    out[row * 64 + c] = fmaxf(acc, 0.f);
}

__global__ __launch_bounds__(32)
void pred_kernel(const float* __restrict__ w, const float* __restrict__ b,
                 const float* __restrict__ in, float* __restrict__ out) {
    __shared__ float sR[64];
    int row = blockIdx.x;
    int c = threadIdx.x;
    sR[c] = in[row * 64 + c];
    sR[c + 32] = in[row * 64 + c + 32];
    __syncthreads();
    float acc = b[c];
    for (int k = 0; k < 64; ++k) acc += sR[k] * w[k * 32 + c];
    out[row * 32 + c] = acc;
}

// =====================================================================
extern "C" void kernel_launch(void* const* d_in, const int* in_sizes, int n_in,
                              void* d_out, int out_size) {
    const float* x       = (const float*)d_in[0];
    const int*   eidx    = (const int*)d_in[1];
    const float* eattr   = (const float*)d_in[2];
    const int*   batch   = (const int*)d_in[3];
    const float* weights = (const float*)d_in[4];
    const int*   subb    = (const int*)d_in[5];
    const float* be_w1   = (const float*)d_in[6];
    const float* be_b1   = (const float*)d_in[7];
    const float* be_w2   = (const float*)d_in[8];
    const float* be_b2   = (const float*)d_in[9];
    const float* mlp_w1  = (const float*)d_in[10];
    const float* mlp_b1  = (const float*)d_in[11];
    const float* mlp_w2  = (const float*)d_in[12];
    const float* mlp_b2  = (const float*)d_in[13];
    const float* epsv    = (const float*)d_in[14];
    const float* bn_g    = (const float*)d_in[15];
    const float* bn_b    = (const float*)d_in[16];
    const float* fc0_w   = (const float*)d_in[17];
    const float* fc0_b   = (const float*)d_in[18];
    const float* fc1_w   = (const float*)d_in[19];
    const float* fc1_b   = (const float*)d_in[20];
    const float* fc2_w   = (const float*)d_in[21];
    const float* fc2_b   = (const float*)d_in[22];
    const float* pred_w  = (const float*)d_in[23];
    const float* pred_b  = (const float*)d_in[24];
    float* out = (float*)d_out;

    void *p_z, *p_agg, *p_bnsum, *p_gsum, *p_gcnt, *p_svec, *p_snorm, *p_t1, *p_t2;
    cudaGetSymbolAddress(&p_z, d_z);
    cudaGetSymbolAddress(&p_agg, d_agg);
    cudaGetSymbolAddress(&p_bnsum, d_bnsum);
    cudaGetSymbolAddress(&p_gsum, d_gsum);
    cudaGetSymbolAddress(&p_gcnt, d_gcnt);
    cudaGetSymbolAddress(&p_svec, d_svec);
    cudaGetSymbolAddress(&p_snorm, d_snorm);
    cudaGetSymbolAddress(&p_t1, d_t1);
    cudaGetSymbolAddress(&p_t2, d_t2);

    cudaFuncSetAttribute(edge_kernel, cudaFuncAttributeMaxDynamicSharedMemorySize,
                         E_SMEM_FLOATS * (int)sizeof(float));
    cudaFuncSetAttribute(node_kernel, cudaFuncAttributeMaxDynamicSharedMemorySize,
                         N_SMEM_FLOATS * (int)sizeof(float));

    cudaMemcpyAsync(p_z, x, (size_t)N_NODES * HID * sizeof(float),
                    cudaMemcpyDeviceToDevice);
    cudaMemsetAsync(p_bnsum, 0, L_LAYERS * 2 * HID * sizeof(float));
    cudaMemsetAsync(p_gsum, 0, (size_t)G_GRAPHS * 192 * sizeof(float));
    cudaMemsetAsync(p_gcnt, 0, G_GRAPHS * sizeof(float));
    cudaMemsetAsync(p_svec, 0, S_SUB * HID * sizeof(float));
    cudaMemsetAsync(p_snorm, 0, S_SUB * sizeof(float));
    count_kernel<<<(N_NODES + 255) / 256, 256>>>(batch);

    const float* bnsum = (const float*)p_bnsum;

    for (int l = 0; l < L_LAYERS; ++l) {
        cudaMemsetAsync(p_agg, 0, (size_t)N_NODES * HID * sizeof(float));
        edge_kernel<<<E_GRID, 128, E_SMEM_FLOATS * sizeof(float)>>>(
            eattr, eidx,
            be_w1 + l * EDGE_F * HID, be_b1 + l * HID,
            be_w2 + l * HID * HID,    be_b2 + l * HID,
            bnsum + (l - 1) * 128, bn_g + (l - 1) * HID, bn_b + (l - 1) * HID,
            l > 0 ? 1 : 0);

        node_kernel<<<N_GRID, 128, N_SMEM_FLOATS * sizeof(float)>>>(
            mlp_w1 + l * HID * HID, mlp_b1 + l * HID,
            mlp_w2 + l * HID * HID, mlp_b2 + l * HID,
            epsv + l,
            bnsum + (l - 1) * 128, bn_g + (l - 1) * HID, bn_b + (l - 1) * HID,
            l > 0 ? 1 : 0, l, batch);
    }

    graph_kernel<<<G_GRAPHS, 64>>>(fc0_w, fc0_b, weights, subb, bn_g, bn_b);
    fc_kernel<<<S_SUB, 64>>>(fc1_w, fc1_b, (const float*)p_svec, (float*)p_t1, 1);
    fc_kernel<<<S_SUB, 64>>>(fc2_w, fc2_b, (const float*)p_t1, (float*)p_t2, 0);
    pred_kernel<<<S_SUB, 32>>>(pred_w, pred_b, (const float*)p_t2, out);
}

// round 10
// speedup vs baseline: 1.4300x; 1.2792x over previous
#include <cuda_runtime.h>
#include <cuda_fp16.h>
#include <cstddef>
#include <cstdint>

#define N_NODES 100000
#define N_EDGES 1000000
#define G_GRAPHS 1024
#define S_SUB 128
#define HID 64
#define EDGE_F 32
#define OUT_F 32
#define L_LAYERS 3
#define BN_EPS 1e-5f

#define E_TILES_TOTAL 15625
#define E_GRID 2048
#define N_TILES 1563
#define N_GRID 512

// u32-unit strides, all == 4 (mod 32) -> conflict-free fragment access
#define ST20 20   // K=32 halves rows
#define ST36 36   // K=64 halves rows
#define SF 68     // fp32 final tile stride

// ---------------- device scratch ----------------
__device__ float d_z[N_NODES * HID];
__device__ float d_agg[N_NODES * HID];
__device__ float d_bnsum[L_LAYERS * 2 * HID];
__device__ float d_gsum[G_GRAPHS * L_LAYERS * HID];
__device__ float d_gcnt[G_GRAPHS];
__device__ float d_svec[S_SUB * HID];
__device__ float d_snorm[S_SUB];
__device__ float d_t1[S_SUB * HID];
__device__ float d_t2[S_SUB * HID];

__device__ __forceinline__ void red4(float* addr, float4 v) {
    asm volatile("red.global.add.v4.f32 [%0], {%1,%2,%3,%4};"
                 :: "l"(addr), "f"(v.x), "f"(v.y), "f"(v.z), "f"(v.w)
                 : "memory");
}

__device__ __forceinline__ uint32_t packh2(float lo, float hi) {
    __half2 h = __floats2half2_rn(lo, hi);
    return *reinterpret_cast<uint32_t*>(&h);
}

// m16n8k16 fp16 mma, fp32 accum, D += A*B
__device__ __forceinline__ void mma16(float* d, uint32_t a0, uint32_t a1,
                                      uint32_t a2, uint32_t a3,
                                      uint32_t b0, uint32_t b1) {
    asm volatile(
        "mma.sync.aligned.m16n8k16.row.col.f32.f16.f16.f32 "
        "{%0,%1,%2,%3}, {%4,%5,%6,%7}, {%8,%9}, {%0,%1,%2,%3};"
        : "+f"(d[0]), "+f"(d[1]), "+f"(d[2]), "+f"(d[3])
        : "r"(a0), "r"(a1), "r"(a2), "r"(a3), "r"(b0), "r"(b1));
}

// ---------------- one-time graph node counts ----------------
__global__ void count_kernel(const int* __restrict__ batch) {
    int i = blockIdx.x * 256 + threadIdx.x;
    if (i < N_NODES) atomicAdd(&d_gcnt[batch[i]], 1.0f);
}

// =====================================================================
// Fused edge kernel: fp16 tensor cores, transposed weights, inline BN
// =====================================================================
// u32 units: W1t 64*20 + W2t 64*36 + B1/B2/AB 256 + Ah 64*20 + Hh 64*36 + Hf 64*68
#define E_SMEM_BYTES ((64*ST20 + 64*ST36 + 256 + 64*ST20 + 64*ST36 + 64*SF) * 4)

__global__ __launch_bounds__(128)
void edge_kernel(const float* __restrict__ edge_attr,
                 const int* __restrict__ eidx,
                 const float* __restrict__ w1, const float* __restrict__ b1,
                 const float* __restrict__ w2, const float* __restrict__ b2,
                 const float* __restrict__ bnsum_prev,
                 const float* __restrict__ gamma_prev,
                 const float* __restrict__ beta_prev, int useBN) {
    extern __shared__ float smem[];
    uint32_t* sW1t = (uint32_t*)smem;            // [64][20] Wt[n][k] halves
    uint32_t* sW2t = sW1t + 64 * ST20;           // [64][36]
    float* sB1 = (float*)(sW2t + 64 * ST36);
    float* sB2 = sB1 + 64;
    float* sAB = sB2 + 64;                       // [128]
    uint32_t* sAh = (uint32_t*)(sAB + 128);      // [64][20] edge tile halves
    uint32_t* sHh = sAh + 64 * ST20;             // [64][36] hidden halves
    float* sHf = (float*)(sHh + 64 * ST36);      // [64][68] fp32 e_out

    const int tid = threadIdx.x;
    const int lane = tid & 31, warp = tid >> 5;
    const int quad = lane >> 2, tq = lane & 3;
    const int r0 = warp * 16;
    const int tc = tid & 7, tr = tid >> 3;
    const int cc = tc * 8, rr = tr * 4;

    // W1t: [n][k] halves, coalesced gather (lane-fastest = n = row dim)
    for (int i = tid; i < 1024; i += 128) {
        int n = i & 63, j = i >> 6;              // j: k-pair 0..15
        sW1t[n * ST20 + j] = packh2(w1[(2 * j) * 64 + n], w1[(2 * j + 1) * 64 + n]);
    }
    for (int i = tid; i < 2048; i += 128) {
        int n = i & 63, j = i >> 6;              // j 0..31
        sW2t[n * ST36 + j] = packh2(w2[(2 * j) * 64 + n], w2[(2 * j + 1) * 64 + n]);
    }
    if (tid < 64) {
        sB1[tid] = b1[tid]; sB2[tid] = b2[tid];
        float a = 1.f, b = 0.f;
        if (useBN) {
            float mu = bnsum_prev[tid] * (1.f / (float)N_NODES);
            float var = bnsum_prev[64 + tid] * (1.f / (float)N_NODES) - mu * mu;
            a = gamma_prev[tid] * rsqrtf(var + BN_EPS);
            b = beta_prev[tid] - mu * a;
        }
        sAB[tid] = a; sAB[64 + tid] = b;
    }
    __syncthreads();

    const float4 ax0 = *((const float4*)(sAB + cc));
    const float4 ax1 = *((const float4*)(sAB + cc + 4));
    const float4 bx0 = *((const float4*)(sAB + 64 + cc));
    const float4 bx1 = *((const float4*)(sAB + 64 + cc + 4));

    for (int tile = blockIdx.x; tile < E_TILES_TOTAL; tile += E_GRID) {
        const int e0 = tile * 64;

        for (int i = tid; i < 512; i += 128) {
            int r = i >> 3, q = i & 7;
            float4 v = ((const float4*)(edge_attr + (size_t)(e0 + r) * EDGE_F))[q];
            sAh[r * ST20 + q * 2]     = packh2(v.x, v.y);
            sAh[r * ST20 + q * 2 + 1] = packh2(v.z, v.w);
        }
        __syncthreads();

        float acc[8][4];
#pragma unroll
        for (int nt = 0; nt < 8; ++nt)
#pragma unroll
            for (int j = 0; j < 4; ++j) acc[nt][j] = 0.f;

        // GEMM1: [64x32] @ [32x64], 2 k-steps
#pragma unroll
        for (int ks = 0; ks < 2; ++ks) {
            uint32_t a0 = sAh[(r0 + quad) * ST20 + ks * 8 + tq];
            uint32_t a1 = sAh[(r0 + quad + 8) * ST20 + ks * 8 + tq];
            uint32_t a2 = sAh[(r0 + quad) * ST20 + ks * 8 + tq + 4];
            uint32_t a3 = sAh[(r0 + quad + 8) * ST20 + ks * 8 + tq + 4];
#pragma unroll
            for (int nt = 0; nt < 8; ++nt) {
                uint32_t b0 = sW1t[(nt * 8 + quad) * ST20 + ks * 8 + tq];
                uint32_t b1v = sW1t[(nt * 8 + quad) * ST20 + ks * 8 + tq + 4];
                mma16(acc[nt], a0, a1, a2, a3, b0, b1v);
            }
        }

        // bias + relu -> sHh (own rows, half2)
#pragma unroll
        for (int nt = 0; nt < 8; ++nt) {
            int c = nt * 8 + 2 * tq;
            sHh[(r0 + quad) * ST36 + nt * 4 + tq] =
                packh2(fmaxf(acc[nt][0] + sB1[c], 0.f),
                       fmaxf(acc[nt][1] + sB1[c + 1], 0.f));
            sHh[(r0 + quad + 8) * ST36 + nt * 4 + tq] =
                packh2(fmaxf(acc[nt][2] + sB1[c], 0.f),
                       fmaxf(acc[nt][3] + sB1[c + 1], 0.f));
        }
        __syncwarp();

#pragma unroll
        for (int nt = 0; nt < 8; ++nt)
#pragma unroll
            for (int j = 0; j < 4; ++j) acc[nt][j] = 0.f;

        // GEMM2: [64x64] @ [64x64], 4 k-steps (A = own rows)
#pragma unroll
        for (int ks = 0; ks < 4; ++ks) {
            uint32_t a0 = sHh[(r0 + quad) * ST36 + ks * 8 + tq];
            uint32_t a1 = sHh[(r0 + quad + 8) * ST36 + ks * 8 + tq];
            uint32_t a2 = sHh[(r0 + quad) * ST36 + ks * 8 + tq + 4];
            uint32_t a3 = sHh[(r0 + quad + 8) * ST36 + ks * 8 + tq + 4];
#pragma unroll
            for (int nt = 0; nt < 8; ++nt) {
                uint32_t b0 = sW2t[(nt * 8 + quad) * ST36 + ks * 8 + tq];
                uint32_t b1v = sW2t[(nt * 8 + quad) * ST36 + ks * 8 + tq + 4];
                mma16(acc[nt], a0, a1, a2, a3, b0, b1v);
            }
        }

        // e + b2 -> sHf (fp32)
#pragma unroll
        for (int nt = 0; nt < 8; ++nt) {
            int c = nt * 8 + 2 * tq;
            sHf[(r0 + quad) * SF + c]         = acc[nt][0] + sB2[c];
            sHf[(r0 + quad) * SF + c + 1]     = acc[nt][1] + sB2[c + 1];
            sHf[(r0 + quad + 8) * SF + c]     = acc[nt][2] + sB2[c];
            sHf[(r0 + quad + 8) * SF + c + 1] = acc[nt][3] + sB2[c + 1];
        }
        __syncthreads();

        // epilogue: msg = relu((z[src]*a+b) + e), scatter to agg[dst]
#pragma unroll
        for (int i = 0; i < 4; ++i) {
            int e = e0 + rr + i;
            int src = eidx[e];
            int dst = eidx[N_EDGES + e];
            const float4* hp = (const float4*)(d_z + (size_t)src * HID + cc);
            float4 h0 = hp[0], h1 = hp[1];
            const float4* ep = (const float4*)(sHf + (rr + i) * SF + cc);
            float4 ev0 = ep[0], ev1 = ep[1];
            float4 m0, m1;
            m0.x = fmaxf(fmaf(h0.x, ax0.x, bx0.x) + ev0.x, 0.f);
            m0.y = fmaxf(fmaf(h0.y, ax0.y, bx0.y) + ev0.y, 0.f);
            m0.z = fmaxf(fmaf(h0.z, ax0.z, bx0.z) + ev0.z, 0.f);
            m0.w = fmaxf(fmaf(h0.w, ax0.w, bx0.w) + ev0.w, 0.f);
            m1.x = fmaxf(fmaf(h1.x, ax1.x, bx1.x) + ev1.x, 0.f);
            m1.y = fmaxf(fmaf(h1.y, ax1.y, bx1.y) + ev1.y, 0.f);
            m1.z = fmaxf(fmaf(h1.z, ax1.z, bx1.z) + ev1.z, 0.f);
            m1.w = fmaxf(fmaf(h1.w, ax1.w, bx1.w) + ev1.w, 0.f);
            red4(d_agg + (size_t)dst * HID + cc, m0);
            red4(d_agg + (size_t)dst * HID + cc + 4, m1);
        }
    }
}

// =====================================================================
// Fused node kernel: fp16 MLP + BN stats + fused graph-pool scatter
// =====================================================================
#define N_SMEM_BYTES ((64*ST36 + 64*ST36 + 256 + 128 + 64*ST36 + 64*ST36 + 64*SF) * 4)

__global__ __launch_bounds__(128)
void node_kernel(const float* __restrict__ w1, const float* __restrict__ b1,
                 const float* __restrict__ w2, const float* __restrict__ b2,
                 const float* __restrict__ epsp,
                 const float* __restrict__ bnsum_prev,
                 const float* __restrict__ gamma_prev,
                 const float* __restrict__ beta_prev, int useBN,
                 int layer, const int* __restrict__ batch) {
    extern __shared__ float smem[];
    uint32_t* sW1t = (uint32_t*)smem;            // [64][36]
    uint32_t* sW2t = sW1t + 64 * ST36;           // [64][36]
    float* sB1 = (float*)(sW2t + 64 * ST36);
    float* sB2 = sB1 + 64;
    float* sSum = sB2 + 64;                      // [64]
    float* sSq  = sSum + 64;                     // [64]
    float* sAB  = sSq + 64;                      // [128]
    uint32_t* sAh = (uint32_t*)(sAB + 128);      // [64][36]
    uint32_t* sHh = sAh + 64 * ST36;             // [64][36]
    float* sHf = (float*)(sHh + 64 * ST36);      // [64][68]

    const int tid = threadIdx.x;
    const int lane = tid & 31, warp = tid >> 5;
    const int quad = lane >> 2, tq = lane & 3;
    const int r0 = warp * 16;
    const int tc = tid & 7, tr = tid >> 3;
    const int cc = tc * 8, rr = tr * 4;
    const float epl = 1.f + epsp[0];

    for (int i = tid; i < 2048; i += 128) {
        int n = i & 63, j = i >> 6;
        sW1t[n * ST36 + j] = packh2(w1[(2 * j) * 64 + n], w1[(2 * j + 1) * 64 + n]);
    }
    for (int i = tid; i < 2048; i += 128) {
        int n = i & 63, j = i >> 6;
        sW2t[n * ST36 + j] = packh2(w2[(2 * j) * 64 + n], w2[(2 * j + 1) * 64 + n]);
    }
    if (tid < 64) {
        sB1[tid] = b1[tid]; sB2[tid] = b2[tid];
        sSum[tid] = 0.f; sSq[tid] = 0.f;
        float a = 1.f, b = 0.f;
        if (useBN) {
            float mu = bnsum_prev[tid] * (1.f / (float)N_NODES);
            float var = bnsum_prev[64 + tid] * (1.f / (float)N_NODES) - mu * mu;
            a = gamma_prev[tid] * rsqrtf(var + BN_EPS);
            b = beta_prev[tid] - mu * a;
        }
        sAB[tid] = a; sAB[64 + tid] = b;
    }
    __syncthreads();

    float csum[8], csq[8];
#pragma unroll
    for (int j = 0; j < 8; ++j) { csum[j] = 0.f; csq[j] = 0.f; }

    for (int tile = blockIdx.x; tile < N_TILES; tile += N_GRID) {
        const int n0 = tile * 64;

        for (int i = tid; i < 1024; i += 128) {
            int r = i >> 4, q = i & 15;
            int n = n0 + r;
            float4 v = make_float4(0.f, 0.f, 0.f, 0.f);
            if (n < N_NODES) {
                float4 zv = ((const float4*)(d_z + (size_t)n * HID))[q];
                float4 av = ((const float4*)(d_agg + (size_t)n * HID))[q];
                float4 aa = ((const float4*)sAB)[q];
                float4 bb = ((const float4*)(sAB + 64))[q];
                v.x = fmaf(zv.x, epl * aa.x, epl * bb.x) + av.x;
                v.y = fmaf(zv.y, epl * aa.y, epl * bb.y) + av.y;
                v.z = fmaf(zv.z, epl * aa.z, epl * bb.z) + av.z;
                v.w = fmaf(zv.w, epl * aa.w, epl * bb.w) + av.w;
            }
            sAh[r * ST36 + q * 2]     = packh2(v.x, v.y);
            sAh[r * ST36 + q * 2 + 1] = packh2(v.z, v.w);
        }
        __syncthreads();

        float acc[8][4];
#pragma unroll
        for (int nt = 0; nt < 8; ++nt)
#pragma unroll
            for (int j = 0; j < 4; ++j) acc[nt][j] = 0.f;

#pragma unroll
        for (int ks = 0; ks < 4; ++ks) {
            uint32_t a0 = sAh[(r0 + quad) * ST36 + ks * 8 + tq];
            uint32_t a1 = sAh[(r0 + quad + 8) * ST36 + ks * 8 + tq];
            uint32_t a2 = sAh[(r0 + quad) * ST36 + ks * 8 + tq + 4];
            uint32_t a3 = sAh[(r0 + quad + 8) * ST36 + ks * 8 + tq + 4];
#pragma unroll
            for (int nt = 0; nt < 8; ++nt) {
                uint32_t b0 = sW1t[(nt * 8 + quad) * ST36 + ks * 8 + tq];
                uint32_t b1v = sW1t[(nt * 8 + quad) * ST36 + ks * 8 + tq + 4];
                mma16(acc[nt], a0, a1, a2, a3, b0, b1v);
            }
        }

#pragma unroll
        for (int nt = 0; nt < 8; ++nt) {
            int c = nt * 8 + 2 * tq;
            sHh[(r0 + quad) * ST36 + nt * 4 + tq] =
                packh2(fmaxf(acc[nt][0] + sB1[c], 0.f),
                       fmaxf(acc[nt][1] + sB1[c + 1], 0.f));
            sHh[(r0 + quad + 8) * ST36 + nt * 4 + tq] =
                packh2(fmaxf(acc[nt][2] + sB1[c], 0.f),
                       fmaxf(acc[nt][3] + sB1[c + 1], 0.f));
        }
        __syncwarp();

#pragma unroll
        for (int nt = 0; nt < 8; ++nt)
#pragma unroll
            for (int j = 0; j < 4; ++j) acc[nt][j] = 0.f;

#pragma unroll
        for (int ks = 0; ks < 4; ++ks) {
            uint32_t a0 = sHh[(r0 + quad) * ST36 + ks * 8 + tq];
            uint32_t a1 = sHh[(r0 + quad + 8) * ST36 + ks * 8 + tq];
            uint32_t a2 = sHh[(r0 + quad) * ST36 + ks * 8 + tq + 4];
            uint32_t a3 = sHh[(r0 + quad + 8) * ST36 + ks * 8 + tq + 4];
#pragma unroll
            for (int nt = 0; nt < 8; ++nt) {
                uint32_t b0 = sW2t[(nt * 8 + quad) * ST36 + ks * 8 + tq];
                uint32_t b1v = sW2t[(nt * 8 + quad) * ST36 + ks * 8 + tq + 4];
                mma16(acc[nt], a0, a1, a2, a3, b0, b1v);
            }
        }

#pragma unroll
        for (int nt = 0; nt < 8; ++nt) {
            int c = nt * 8 + 2 * tq;
            sHf[(r0 + quad) * SF + c]         = acc[nt][0] + sB2[c];
            sHf[(r0 + quad) * SF + c + 1]     = acc[nt][1] + sB2[c + 1];
            sHf[(r0 + quad + 8) * SF + c]     = acc[nt][2] + sB2[c];
            sHf[(r0 + quad + 8) * SF + c + 1] = acc[nt][3] + sB2[c + 1];
        }
        __syncthreads();

        // epilogue: relu, write z, BN sums, run-reduced graph-pool scatter
        float racc[8];
#pragma unroll
        for (int j = 0; j < 8; ++j) racc[j] = 0.f;
        int curg = -1;

#pragma unroll
        for (int i = 0; i < 4; ++i) {
            int n = n0 + rr + i;
            if (n < N_NODES) {
                int g = batch[n];
                if (g != curg) {
                    if (curg >= 0) {
                        float* gp = d_gsum + (size_t)curg * (L_LAYERS * HID)
                                    + layer * HID + cc;
                        red4(gp, make_float4(racc[0], racc[1], racc[2], racc[3]));
                        red4(gp + 4, make_float4(racc[4], racc[5], racc[6], racc[7]));
#pragma unroll
                        for (int j = 0; j < 8; ++j) racc[j] = 0.f;
                    }
                    curg = g;
                }
                const float* ev = sHf + (rr + i) * SF + cc;
                float zv[8];
#pragma unroll
                for (int j = 0; j < 8; ++j) {
                    zv[j] = fmaxf(ev[j], 0.f);
                    csum[j] += zv[j];
                    csq[j] += zv[j] * zv[j];
                    racc[j] += zv[j];
                }
                float4* zp = (float4*)(d_z + (size_t)n * HID + cc);
                zp[0] = make_float4(zv[0], zv[1], zv[2], zv[3]);
                zp[1] = make_float4(zv[4], zv[5], zv[6], zv[7]);
            }
        }
        if (curg >= 0) {
            float* gp = d_gsum + (size_t)curg * (L_LAYERS * HID) + layer * HID + cc;
            red4(gp, make_float4(racc[0], racc[1], racc[2], racc[3]));
            red4(gp + 4, make_float4(racc[4], racc[5], racc[6], racc[7]));
        }
    }

    __syncthreads();
#pragma unroll
    for (int j = 0; j < 8; ++j) {
        atomicAdd(&sSum[cc + j], csum[j]);
        atomicAdd(&sSq[cc + j], csq[j]);
    }
    __syncthreads();
    if (tid < 64) {
        atomicAdd(&d_bnsum[layer * 128 + tid], sSum[tid]);
        atomicAdd(&d_bnsum[layer * 128 + 64 + tid], sSq[tid]);
    }
}

// ---------------- per-graph fc0 (+inline BN affine) + scatter ----------------
__global__ __launch_bounds__(64)
void graph_kernel(const float* __restrict__ fc0w, const float* __restrict__ fc0b,
                  const float* __restrict__ gweights, const int* __restrict__ subb,
                  const float* __restrict__ bn_g, const float* __restrict__ bn_b) {
    __shared__ float sG[192];
    __shared__ float sAB[2 * 192];
    int g = blockIdx.x;
    int c = threadIdx.x;

    for (int l = 0; l < L_LAYERS; ++l) {
        float mu = d_bnsum[l * 128 + c] * (1.f / (float)N_NODES);
        float var = d_bnsum[l * 128 + 64 + c] * (1.f / (float)N_NODES) - mu * mu;
        float a = bn_g[l * 64 + c] * rsqrtf(var + BN_EPS);
        sAB[l * 64 + c] = a;
        sAB[192 + l * 64 + c] = bn_b[l * 64 + c] - mu * a;
    }
    __syncthreads();

    float inv = 1.f / fmaxf(d_gcnt[g], 1.f);
    for (int i = c; i < 192; i += 64)
        sG[i] = fmaf(d_gsum[(size_t)g * 192 + i] * inv, sAB[i], sAB[192 + i]);
    __syncthreads();

    float acc = fc0b[c];
    for (int k = 0; k < 192; ++k) acc += sG[k] * fc0w[k * 64 + c];
    float w = gweights[g];
    float v = fmaxf(acc, 0.f) * w;
    int s = subb[g];
    atomicAdd(&d_svec[s * 64 + c], v);
    if (c == 0) atomicAdd(&d_snorm[s], w);
}

// ---------------- subgraph FC layers ----------------
__global__ __launch_bounds__(64)
void fc_kernel(const float* __restrict__ w, const float* __restrict__ b,
               const float* __restrict__ in, float* __restrict__ out,
               int normalize) {
    __shared__ float sR[64];
    int row = blockIdx.x;
    int c = threadIdx.x;
    float v = in[row * 64 + c];
    if (normalize) v = v / fmaxf(d_snorm[row], 1e-12f);
    sR[c] = v;
    __syncthreads();
    float acc = b[c];
    for (int k = 0; k < 64; ++k) acc += sR[k] * w[k * 64 + c];
    out[row * 64 + c] = fmaxf(acc, 0.f);
}

__global__ __launch_bounds__(32)
void pred_kernel(const float* __restrict__ w, const float* __restrict__ b,
                 const float* __restrict__ in, float* __restrict__ out) {
    __shared__ float sR[64];
    int row = blockIdx.x;
    int c = threadIdx.x;
    sR[c] = in[row * 64 + c];
    sR[c + 32] = in[row * 64 + c + 32];
    __syncthreads();
    float acc = b[c];
    for (int k = 0; k < 64; ++k) acc += sR[k] * w[k * 32 + c];
    out[row * 32 + c] = acc;
}

// =====================================================================
extern "C" void kernel_launch(void* const* d_in, const int* in_sizes, int n_in,
                              void* d_out, int out_size) {
    const float* x       = (const float*)d_in[0];
    const int*   eidx    = (const int*)d_in[1];
    const float* eattr   = (const float*)d_in[2];
    const int*   batch   = (const int*)d_in[3];
    const float* weights = (const float*)d_in[4];
    const int*   subb    = (const int*)d_in[5];
    const float* be_w1   = (const float*)d_in[6];
    const float* be_b1   = (const float*)d_in[7];
    const float* be_w2   = (const float*)d_in[8];
    const float* be_b2   = (const float*)d_in[9];
    const float* mlp_w1  = (const float*)d_in[10];
    const float* mlp_b1  = (const float*)d_in[11];
    const float* mlp_w2  = (const float*)d_in[12];
    const float* mlp_b2  = (const float*)d_in[13];
    const float* epsv    = (const float*)d_in[14];
    const float* bn_g    = (const float*)d_in[15];
    const float* bn_b    = (const float*)d_in[16];
    const float* fc0_w   = (const float*)d_in[17];
    const float* fc0_b   = (const float*)d_in[18];
    const float* fc1_w   = (const float*)d_in[19];
    const float* fc1_b   = (const float*)d_in[20];
    const float* fc2_w   = (const float*)d_in[21];
    const float* fc2_b   = (const float*)d_in[22];
    const float* pred_w  = (const float*)d_in[23];
    const float* pred_b  = (const float*)d_in[24];
    float* out = (float*)d_out;

    void *p_z, *p_agg, *p_bnsum, *p_gsum, *p_gcnt, *p_svec, *p_snorm, *p_t1, *p_t2;
    cudaGetSymbolAddress(&p_z, d_z);
    cudaGetSymbolAddress(&p_agg, d_agg);
    cudaGetSymbolAddress(&p_bnsum, d_bnsum);
    cudaGetSymbolAddress(&p_gsum, d_gsum);
    cudaGetSymbolAddress(&p_gcnt, d_gcnt);
    cudaGetSymbolAddress(&p_svec, d_svec);
    cudaGetSymbolAddress(&p_snorm, d_snorm);
    cudaGetSymbolAddress(&p_t1, d_t1);
    cudaGetSymbolAddress(&p_t2, d_t2);

    cudaFuncSetAttribute(edge_kernel, cudaFuncAttributeMaxDynamicSharedMemorySize,
                         E_SMEM_BYTES);
    cudaFuncSetAttribute(node_kernel, cudaFuncAttributeMaxDynamicSharedMemorySize,
                         N_SMEM_BYTES);

    cudaMemcpyAsync(p_z, x, (size_t)N_NODES * HID * sizeof(float),
                    cudaMemcpyDeviceToDevice);
    cudaMemsetAsync(p_bnsum, 0, L_LAYERS * 2 * HID * sizeof(float));
    cudaMemsetAsync(p_gsum, 0, (size_t)G_GRAPHS * 192 * sizeof(float));
    cudaMemsetAsync(p_gcnt, 0, G_GRAPHS * sizeof(float));
    cudaMemsetAsync(p_svec, 0, S_SUB * HID * sizeof(float));
    cudaMemsetAsync(p_snorm, 0, S_SUB * sizeof(float));
    count_kernel<<<(N_NODES + 255) / 256, 256>>>(batch);

    const float* bnsum = (const float*)p_bnsum;

    for (int l = 0; l < L_LAYERS; ++l) {
        cudaMemsetAsync(p_agg, 0, (size_t)N_NODES * HID * sizeof(float));
        edge_kernel<<<E_GRID, 128, E_SMEM_BYTES>>>(
            eattr, eidx,
            be_w1 + l * EDGE_F * HID, be_b1 + l * HID,
            be_w2 + l * HID * HID,    be_b2 + l * HID,
            bnsum + (l - 1) * 128, bn_g + (l - 1) * HID, bn_b + (l - 1) * HID,
            l > 0 ? 1 : 0);

        node_kernel<<<N_GRID, 128, N_SMEM_BYTES>>>(
            mlp_w1 + l * HID * HID, mlp_b1 + l * HID,
            mlp_w2 + l * HID * HID, mlp_b2 + l * HID,
            epsv + l,
            bnsum + (l - 1) * 128, bn_g + (l - 1) * HID, bn_b + (l - 1) * HID,
            l > 0 ? 1 : 0, l, batch);
    }

    graph_kernel<<<G_GRAPHS, 64>>>(fc0_w, fc0_b, weights, subb, bn_g, bn_b);
    fc_kernel<<<S_SUB, 64>>>(fc1_w, fc1_b, (const float*)p_svec, (float*)p_t1, 1);
    fc_kernel<<<S_SUB, 64>>>(fc2_w, fc2_b, (const float*)p_t1, (float*)p_t2, 0);
    pred_kernel<<<S_SUB, 32>>>(pred_w, pred_b, (const float*)p_t2, out);
}